// round 5
// baseline (speedup 1.0000x reference)
#include <cuda_runtime.h>
#include <cuda_bf16.h>
#include <cstdint>

#define N_ROWS 200000
#define HID    512
#define HHALF  256
#define NG     2000
#define MROWS  128
#define KC     64
#define NCHUNK 8
#define NTHREADS 512

// smem byte offsets
#define OFF_B1    0
#define OFF_W2    1024
#define OFF_ALPHA 2048      // 128*8*4 = 4KB
#define OFF_RSUM  6144      // 512B
#define OFF_A     8192      // 2 stages * 32KB (hi 16KB + lo 16KB)
#define A_STG     32768
#define A_LO      16384
#define OFF_B     73728     // 2 stages * 64KB (hi 32KB + lo 32KB)
#define B_STG     65536
#define B_LO      32768
#define SMEM_TOTAL 204800

__device__ __nv_bfloat16 g_W1hi[HHALF * HID];
__device__ __nv_bfloat16 g_W1lo[HHALF * HID];

// ---------------- helpers ----------------
__device__ __forceinline__ uint32_t smem_u32(const void* p) {
    uint32_t a;
    asm("{ .reg .u64 t; cvta.to.shared.u64 t, %1; cvt.u32.u64 %0, t; }" : "=r"(a) : "l"(p));
    return a;
}
#define LDSM4(r, a) asm volatile("ldmatrix.sync.aligned.m8n8.x4.shared.b16 {%0,%1,%2,%3}, [%4];" \
    : "=r"((r)[0]),"=r"((r)[1]),"=r"((r)[2]),"=r"((r)[3]) : "r"(a))
#define MMA16816(d, a, b0, b1) asm volatile( \
    "mma.sync.aligned.m16n8k16.row.col.f32.bf16.bf16.f32 " \
    "{%0,%1,%2,%3}, {%4,%5,%6,%7}, {%8,%9}, {%0,%1,%2,%3};" \
    : "+f"((d)[0]),"+f"((d)[1]),"+f"((d)[2]),"+f"((d)[3]) \
    : "r"((a)[0]),"r"((a)[1]),"r"((a)[2]),"r"((a)[3]), "r"(b0),"r"(b1))
#define CPASYNC16(dst, src) asm volatile("cp.async.cg.shared.global [%0], [%1], 16;" :: "r"(dst), "l"(src) : "memory")
#define CPCOMMIT() asm volatile("cp.async.commit_group;" ::: "memory")
#define CPWAIT0()  asm volatile("cp.async.wait_group 0;" ::: "memory")

__device__ __forceinline__ uint32_t pack_bf16x2(float e_lo, float e_hi) {
    uint32_t r;
    asm("cvt.rn.bf16x2.f32 %0, %1, %2;" : "=r"(r) : "f"(e_hi), "f"(e_lo));
    return r;
}
__device__ __forceinline__ float bflo_f(uint32_t p) { return __uint_as_float(p << 16); }
__device__ __forceinline__ float bfhi_f(uint32_t p) { return __uint_as_float(p & 0xffff0000u); }
__device__ __forceinline__ float silu_f(float z) { return __fdividef(z, 1.0f + __expf(-z)); }

// ---------------- prep kernel (zero out + split W1) ----------------
__global__ void prep_kernel(const float* __restrict__ W1, float* __restrict__ out) {
    int i = blockIdx.x * blockDim.x + threadIdx.x;
    if (i < NG) out[i] = 0.0f;
    if (i < HHALF * HID) {
        float x = W1[i];
        __nv_bfloat16 hi = __float2bfloat16(x);
        g_W1hi[i] = hi;
        g_W1lo[i] = __float2bfloat16(x - __bfloat162float(hi));
    }
}

// ---------------- device helpers ----------------
__device__ __forceinline__ void stage_B(uint32_t sbase, int st, int kk, int tid) {
    #pragma unroll
    for (int j = 0; j < 8; ++j) {
        int task = tid + j * 512;
        int hl   = task >> 11;
        int rem  = task & 2047;
        int n    = rem >> 3;
        int unit = rem & 7;
        const __nv_bfloat16* src = (hl ? g_W1lo : g_W1hi) + n * HID + kk + unit * 8;
        uint32_t dst = sbase + OFF_B + st * B_STG + hl * B_LO + n * 128
                     + (((unsigned)(unit ^ (n & 7))) << 4);
        CPASYNC16(dst, src);
    }
    CPCOMMIT();
}

__device__ __forceinline__ void load_va(float4 va[2][2], const float* __restrict__ h,
                                        int row0, int tid, int kk) {
    const int slot = tid & 7;
    #pragma unroll
    for (int i = 0; i < 2; ++i) {
        int row = (tid >> 3) + i * 64;
        int grow = row0 + row;
        if (grow < N_ROWS) {
            const float* p = h + (size_t)grow * HID + kk + slot * 8;
            va[i][0] = __ldg((const float4*)p);
            va[i][1] = __ldg((const float4*)(p + 4));
        } else {
            va[i][0] = make_float4(0.f, 0.f, 0.f, 0.f);
            va[i][1] = va[i][0];
        }
    }
}

__device__ __forceinline__ void convert_chunk(char* smem, uint32_t abytes,
                                              const float4 va[2][2],
                                              const float* __restrict__ Ww,
                                              int kk, int tid, float* aacc) {
    const int slot = tid & 7;
    float4 wk0 = __ldg((const float4*)(Ww + kk + slot * 8));
    float4 wk1 = __ldg((const float4*)(Ww + kk + slot * 8 + 4));
    #pragma unroll
    for (int i = 0; i < 2; ++i) {
        int row = (tid >> 3) + i * 64;
        float4 v0 = va[i][0], v1 = va[i][1];
        aacc[i] = fmaf(v0.x, wk0.x, fmaf(v0.y, wk0.y, fmaf(v0.z, wk0.z, fmaf(v0.w, wk0.w, aacc[i]))));
        aacc[i] = fmaf(v1.x, wk1.x, fmaf(v1.y, wk1.y, fmaf(v1.z, wk1.z, fmaf(v1.w, wk1.w, aacc[i]))));
        uint32_t h0 = pack_bf16x2(v0.x, v0.y), h1 = pack_bf16x2(v0.z, v0.w);
        uint32_t h2 = pack_bf16x2(v1.x, v1.y), h3 = pack_bf16x2(v1.z, v1.w);
        uint32_t l0 = pack_bf16x2(v0.x - bflo_f(h0), v0.y - bfhi_f(h0));
        uint32_t l1 = pack_bf16x2(v0.z - bflo_f(h1), v0.w - bfhi_f(h1));
        uint32_t l2 = pack_bf16x2(v1.x - bflo_f(h2), v1.y - bfhi_f(h2));
        uint32_t l3 = pack_bf16x2(v1.z - bflo_f(h3), v1.w - bfhi_f(h3));
        uint32_t off = (unsigned)row * 128 + (((unsigned)(slot ^ (row & 7))) << 4);
        *(uint4*)(smem + abytes + off)        = make_uint4(h0, h1, h2, h3);
        *(uint4*)(smem + abytes + A_LO + off) = make_uint4(l0, l1, l2, l3);
    }
}

// ---------------- main kernel ----------------
__global__ __launch_bounds__(NTHREADS, 1)
void fused_mma_kernel(
    const float* __restrict__ h,
    const void*  __restrict__ batch_raw,
    const float* __restrict__ b1,
    const float* __restrict__ W2,
    const float* __restrict__ b2,
    const float* __restrict__ Ww,
    const float* __restrict__ bw,
    float* __restrict__ out)
{
    extern __shared__ char smem[];
    const uint32_t sbase = smem_u32(smem);
    const int tid = threadIdx.x;
    const int wid = tid >> 5, lid = tid & 31;
    const int row0 = blockIdx.x * MROWS;

    float* b1s  = (float*)(smem + OFF_B1);
    float* w2s  = (float*)(smem + OFF_W2);
    float* alps = (float*)(smem + OFF_ALPHA);
    float* rsum = (float*)(smem + OFF_RSUM);

    if (tid < 256) { b1s[tid] = b1[tid]; w2s[tid] = W2[tid]; }
    if (tid < 128) rsum[tid] = 0.0f;

    const bool is64 = (((const int*)batch_raw)[N_ROWS - 1] == 0);

    // warp layout: 4 x 4 grid of 32x64 tiles
    const int wm = wid >> 2;          // 0..3
    const int wn = wid & 3;           // 0..3
    const int arow_lane = wm * 32 + (lid & 15);
    const int a_uhalf   = lid >> 4;
    const int b_nlane   = wn * 64 + (lid & 7) + ((lid >> 4) << 3);
    const int b_uhalf   = (lid >> 3) & 1;

    float acc[2][8][4];
    #pragma unroll
    for (int a = 0; a < 2; ++a)
        #pragma unroll
        for (int b = 0; b < 8; ++b)
            #pragma unroll
            for (int c = 0; c < 4; ++c) acc[a][b][c] = 0.0f;

    float aacc[2] = {0.f, 0.f};
    float4 va[2][2];

    // ---------------- prologue: stage chunk 0 ----------------
    stage_B(sbase, 0, 0, tid);
    load_va(va, h, row0, tid, 0);
    convert_chunk(smem, OFF_A, va, Ww, 0, tid, aacc);
    CPWAIT0();
    __syncthreads();

    // ---------------- main loop ----------------
    for (int c = 0; c < NCHUNK; ++c) {
        const int s = c & 1;
        const bool more = (c + 1) < NCHUNK;
        if (more) {
            stage_B(sbase, s ^ 1, (c + 1) * KC, tid);
            load_va(va, h, row0, tid, (c + 1) * KC);
        }

        const uint32_t abase = sbase + OFF_A + s * A_STG;
        const uint32_t bbase = sbase + OFF_B + s * B_STG;

        #pragma unroll
        for (int ks = 0; ks < 4; ++ks) {
            uint32_t ah[2][4], aL[2][4], bb[4][4];
            // A-hi, B-hi
            #pragma unroll
            for (int mt = 0; mt < 2; ++mt) {
                int row = arow_lane + mt * 16;
                uint32_t u = (uint32_t)((ks * 2 + a_uhalf) ^ (row & 7));
                LDSM4(ah[mt], abase + (unsigned)row * 128 + (u << 4));
            }
            #pragma unroll
            for (int p = 0; p < 4; ++p) {
                int n = b_nlane + p * 16;
                uint32_t u = (uint32_t)((ks * 2 + b_uhalf) ^ (n & 7));
                LDSM4(bb[p], bbase + (unsigned)n * 128 + (u << 4));
            }
            #pragma unroll
            for (int mt = 0; mt < 2; ++mt)
                #pragma unroll
                for (int nt = 0; nt < 8; ++nt)
                    MMA16816(acc[mt][nt], ah[mt], bb[nt >> 1][(nt & 1) * 2], bb[nt >> 1][(nt & 1) * 2 + 1]);
            // A-lo x B-hi
            #pragma unroll
            for (int mt = 0; mt < 2; ++mt) {
                int row = arow_lane + mt * 16;
                uint32_t u = (uint32_t)((ks * 2 + a_uhalf) ^ (row & 7));
                LDSM4(aL[mt], abase + A_LO + (unsigned)row * 128 + (u << 4));
            }
            #pragma unroll
            for (int mt = 0; mt < 2; ++mt)
                #pragma unroll
                for (int nt = 0; nt < 8; ++nt)
                    MMA16816(acc[mt][nt], aL[mt], bb[nt >> 1][(nt & 1) * 2], bb[nt >> 1][(nt & 1) * 2 + 1]);
            // A-hi x B-lo (reuse bb)
            #pragma unroll
            for (int p = 0; p < 4; ++p) {
                int n = b_nlane + p * 16;
                uint32_t u = (uint32_t)((ks * 2 + b_uhalf) ^ (n & 7));
                LDSM4(bb[p], bbase + B_LO + (unsigned)n * 128 + (u << 4));
            }
            #pragma unroll
            for (int mt = 0; mt < 2; ++mt)
                #pragma unroll
                for (int nt = 0; nt < 8; ++nt)
                    MMA16816(acc[mt][nt], ah[mt], bb[nt >> 1][(nt & 1) * 2], bb[nt >> 1][(nt & 1) * 2 + 1]);
        }

        if (more) {
            convert_chunk(smem, OFF_A + (s ^ 1) * A_STG, va, Ww, (c + 1) * KC, tid, aacc);
            CPWAIT0();
        }
        __syncthreads();
    }

    // ---------------- epilogue ----------------
    // alpha partials -> smem
    {
        const int slot = tid & 7;
        #pragma unroll
        for (int i = 0; i < 2; ++i) {
            int row = (tid >> 3) + i * 64;
            alps[row * 8 + slot] = aacc[i];
        }
    }

    // rowsum partials: silu + W2 over this warp's 64 cols
    {
        #pragma unroll
        for (int mt = 0; mt < 2; ++mt) {
            float p0 = 0.0f, p1 = 0.0f;
            #pragma unroll
            for (int nt = 0; nt < 8; ++nt) {
                int col = wn * 64 + nt * 8 + 2 * (lid & 3);
                float bA = b1s[col], bB = b1s[col + 1];
                float wA = w2s[col], wB = w2s[col + 1];
                p0 += silu_f(acc[mt][nt][0] + bA) * wA + silu_f(acc[mt][nt][1] + bB) * wB;
                p1 += silu_f(acc[mt][nt][2] + bA) * wA + silu_f(acc[mt][nt][3] + bB) * wB;
            }
            p0 += __shfl_xor_sync(0xffffffffu, p0, 1);
            p0 += __shfl_xor_sync(0xffffffffu, p0, 2);
            p1 += __shfl_xor_sync(0xffffffffu, p1, 1);
            p1 += __shfl_xor_sync(0xffffffffu, p1, 2);
            if ((lid & 3) == 0) {
                int r = wm * 32 + mt * 16 + (lid >> 2);
                atomicAdd(&rsum[r], p0);
                atomicAdd(&rsum[r + 8], p1);
            }
        }
    }
    __syncthreads();

    // final: gate + segment sum (warps 0-3)
    if (tid < 128) {
        const int row = tid, grow = row0 + row;
        const bool valid = grow < N_ROWS;
        float alr = 0.0f;
        #pragma unroll
        for (int s2 = 0; s2 < 8; ++s2) alr += alps[row * 8 + s2];
        const float b2v = __ldg(b2), bwv = __ldg(bw);
        float val = valid ? (rsum[row] + b2v) * (alr + bwv) : 0.0f;
        int g = valid
            ? (is64 ? (int)((const long long*)batch_raw)[grow] : ((const int*)batch_raw)[grow])
            : -1;
        float tot = 0.0f;
        #pragma unroll
        for (int k2 = 0; k2 < 32; ++k2) {
            float vk = __shfl_sync(0xffffffffu, val, k2);
            int   gk = __shfl_sync(0xffffffffu, g, k2);
            if (gk == g) tot += vk;
        }
        int gp = __shfl_up_sync(0xffffffffu, g, 1);
        if (valid && (lid == 0 || g != gp)) atomicAdd(out + g, tot);
    }
}

// ---------------- launch ----------------
extern "C" void kernel_launch(void* const* d_in, const int* in_sizes, int n_in,
                              void* d_out, int out_size) {
    const float* h     = (const float*)d_in[0];
    const void*  batch = d_in[3];
    const float* W1    = (const float*)d_in[5];
    const float* b1    = (const float*)d_in[6];
    const float* W2    = (const float*)d_in[7];
    const float* b2    = (const float*)d_in[8];
    const float* Ww    = (const float*)d_in[9];
    const float* bw    = (const float*)d_in[10];
    float* out = (float*)d_out;

    cudaFuncSetAttribute(fused_mma_kernel,
                         cudaFuncAttributeMaxDynamicSharedMemorySize, SMEM_TOTAL);

    prep_kernel<<<(HHALF * HID) / 256, 256>>>(W1, out);

    int grid = (N_ROWS + MROWS - 1) / MROWS;   // 1563
    fused_mma_kernel<<<grid, NTHREADS, SMEM_TOTAL>>>(h, batch, b1, W2, b2, Ww, bw, out);
}

// round 6
// speedup vs baseline: 1.2649x; 1.2649x over previous
#include <cuda_runtime.h>
#include <cuda_fp16.h>
#include <cstdint>

#define N_ROWS 200000
#define HID    512
#define HHALF  256
#define NG     2000
#define MROWS  128
#define KC     128
#define NCHUNK 4
#define NTHREADS 512

// smem byte offsets
#define OFF_B1    0
#define OFF_W2    1024
#define OFF_ALPHA 2048      // 128*4 floats
#define OFF_RSUM  6144
#define OFF_A     8192      // 2 stages x (2 planes x 16KB)
#define A_STG     32768
#define A_PLANE   16384
#define OFF_B     73728     // 2 stages x (2 planes x 32KB)
#define B_STG     65536
#define B_PLANE   32768
#define SMEM_TOTAL 204800

__device__ __half g_W1h[HHALF * HID];

// ---------------- helpers ----------------
__device__ __forceinline__ uint32_t smem_u32(const void* p) {
    uint32_t a;
    asm("{ .reg .u64 t; cvta.to.shared.u64 t, %1; cvt.u32.u64 %0, t; }" : "=r"(a) : "l"(p));
    return a;
}
#define LDSM4(r, a) asm volatile("ldmatrix.sync.aligned.m8n8.x4.shared.b16 {%0,%1,%2,%3}, [%4];" \
    : "=r"((r)[0]),"=r"((r)[1]),"=r"((r)[2]),"=r"((r)[3]) : "r"(a))
#define MMA16816(d, a, b0, b1) asm volatile( \
    "mma.sync.aligned.m16n8k16.row.col.f32.f16.f16.f32 " \
    "{%0,%1,%2,%3}, {%4,%5,%6,%7}, {%8,%9}, {%0,%1,%2,%3};" \
    : "+f"((d)[0]),"+f"((d)[1]),"+f"((d)[2]),"+f"((d)[3]) \
    : "r"((a)[0]),"r"((a)[1]),"r"((a)[2]),"r"((a)[3]), "r"(b0),"r"(b1))
#define CPASYNC16(dst, src) asm volatile("cp.async.cg.shared.global [%0], [%1], 16;" :: "r"(dst), "l"(src) : "memory")
#define CPCOMMIT() asm volatile("cp.async.commit_group;" ::: "memory")
#define CPWAIT0()  asm volatile("cp.async.wait_group 0;" ::: "memory")

__device__ __forceinline__ uint32_t pack_f16x2(float e_lo, float e_hi) {
    uint32_t r;
    asm("cvt.rn.f16x2.f32 %0, %1, %2;" : "=r"(r) : "f"(e_hi), "f"(e_lo));
    return r;
}
__device__ __forceinline__ float silu_f(float z) { return __fdividef(z, 1.0f + __expf(-z)); }

// ---------------- prep kernel (zero out + W1 -> fp16) ----------------
__global__ void prep_kernel(const float* __restrict__ W1, float* __restrict__ out) {
    int i = blockIdx.x * blockDim.x + threadIdx.x;
    if (i < NG) out[i] = 0.0f;
    if (i < HHALF * HID) g_W1h[i] = __float2half(W1[i]);
}

// ---------------- device helpers ----------------
__device__ __forceinline__ void stage_B(uint32_t sbase, int st, int kk, int tid) {
    #pragma unroll
    for (int j = 0; j < 8; ++j) {
        int kh   = j >> 2;
        int task = tid + (j & 3) * 512;   // 0..2047
        int n    = task >> 3;
        int unit = task & 7;
        const __half* src = g_W1h + n * HID + kk + kh * 64 + unit * 8;
        uint32_t dst = sbase + OFF_B + st * B_STG + kh * B_PLANE + n * 128
                     + (((unsigned)(unit ^ (n & 7))) << 4);
        CPASYNC16(dst, src);
    }
    CPCOMMIT();
}

__device__ __forceinline__ void load_va(float4 va[8], const float* __restrict__ h,
                                        int row0, int tid, int kk) {
    const int arow = tid >> 2;
    const int q    = tid & 3;
    const int grow = row0 + arow;
    if (grow < N_ROWS) {
        const float* p = h + (size_t)grow * HID + kk + q * 32;
        #pragma unroll
        for (int i = 0; i < 8; ++i) va[i] = __ldg((const float4*)(p + i * 4));
    } else {
        #pragma unroll
        for (int i = 0; i < 8; ++i) va[i] = make_float4(0.f, 0.f, 0.f, 0.f);
    }
}

__device__ __forceinline__ void convert_chunk(char* smem, uint32_t abytes,
                                              const float4 va[8],
                                              const float* __restrict__ Ww,
                                              int kk, int tid, float& aacc) {
    const int arow = tid >> 2;
    const int q    = tid & 3;
    const int kh   = q >> 1;
    // alpha GEMV partial over this thread's 32 k-values
    float a = 0.0f;
    #pragma unroll
    for (int i = 0; i < 8; ++i) {
        float4 w = __ldg((const float4*)(Ww + kk + q * 32 + i * 4));
        float4 v = va[i];
        a = fmaf(v.x, w.x, fmaf(v.y, w.y, fmaf(v.z, w.z, fmaf(v.w, w.w, a))));
    }
    aacc += a;
    // fp16 pack: 4 stores of 16B (8 fp16 each)
    #pragma unroll
    for (int p = 0; p < 4; ++p) {
        float4 v0 = va[2 * p], v1 = va[2 * p + 1];
        uint4 pk = make_uint4(pack_f16x2(v0.x, v0.y), pack_f16x2(v0.z, v0.w),
                              pack_f16x2(v1.x, v1.y), pack_f16x2(v1.z, v1.w));
        uint32_t u = (unsigned)((q & 1) * 4 + p);
        uint32_t off = (unsigned)arow * 128 + (((u ^ (arow & 7))) << 4);
        *(uint4*)(smem + abytes + kh * A_PLANE + off) = pk;
    }
}

// ---------------- main kernel ----------------
__global__ __launch_bounds__(NTHREADS, 1)
void fused_mma_kernel(
    const float* __restrict__ h,
    const void*  __restrict__ batch_raw,
    const float* __restrict__ b1,
    const float* __restrict__ W2,
    const float* __restrict__ b2,
    const float* __restrict__ Ww,
    const float* __restrict__ bw,
    float* __restrict__ out)
{
    extern __shared__ char smem[];
    const uint32_t sbase = smem_u32(smem);
    const int tid = threadIdx.x;
    const int wid = tid >> 5, lid = tid & 31;
    const int row0 = blockIdx.x * MROWS;

    float* b1s  = (float*)(smem + OFF_B1);
    float* w2s  = (float*)(smem + OFF_W2);
    float* alps = (float*)(smem + OFF_ALPHA);
    float* rsum = (float*)(smem + OFF_RSUM);

    if (tid < 256) { b1s[tid] = b1[tid]; w2s[tid] = W2[tid]; }
    if (tid < 128) rsum[tid] = 0.0f;

    const bool is64 = (((const int*)batch_raw)[N_ROWS - 1] == 0);

    // warp layout: 4 x 4 grid of 32x64 tiles
    const int wm = wid >> 2;
    const int wn = wid & 3;
    const int arow_lane = wm * 32 + (lid & 15);
    const int a_uhalf   = lid >> 4;
    const int b_nlane   = wn * 64 + (lid & 7) + ((lid >> 4) << 3);
    const int b_uhalf   = (lid >> 3) & 1;

    float acc[2][8][4];
    #pragma unroll
    for (int a = 0; a < 2; ++a)
        #pragma unroll
        for (int b = 0; b < 8; ++b)
            #pragma unroll
            for (int c = 0; c < 4; ++c) acc[a][b][c] = 0.0f;

    float aacc = 0.0f;
    float4 va[8];

    // ---------------- prologue ----------------
    stage_B(sbase, 0, 0, tid);
    load_va(va, h, row0, tid, 0);
    convert_chunk(smem, OFF_A, va, Ww, 0, tid, aacc);
    CPWAIT0();
    __syncthreads();

    // ---------------- main loop ----------------
    for (int c = 0; c < NCHUNK; ++c) {
        const int s = c & 1;
        const bool more = (c + 1) < NCHUNK;
        if (more) {
            stage_B(sbase, s ^ 1, (c + 1) * KC, tid);
            load_va(va, h, row0, tid, (c + 1) * KC);
        }

        const uint32_t abase = sbase + OFF_A + s * A_STG;
        const uint32_t bbase = sbase + OFF_B + s * B_STG;

        // first half: ks 0..3 (plane 0)
        #pragma unroll
        for (int ks = 0; ks < 4; ++ks) {
            uint32_t ah[2][4], bb[4][4];
            #pragma unroll
            for (int mt = 0; mt < 2; ++mt) {
                int row = arow_lane + mt * 16;
                uint32_t u = (uint32_t)((ks * 2 + a_uhalf) ^ (row & 7));
                LDSM4(ah[mt], abase + (unsigned)row * 128 + (u << 4));
            }
            #pragma unroll
            for (int p = 0; p < 4; ++p) {
                int n = b_nlane + p * 16;
                uint32_t u = (uint32_t)((ks * 2 + b_uhalf) ^ (n & 7));
                LDSM4(bb[p], bbase + (unsigned)n * 128 + (u << 4));
            }
            #pragma unroll
            for (int mt = 0; mt < 2; ++mt)
                #pragma unroll
                for (int nt = 0; nt < 8; ++nt)
                    MMA16816(acc[mt][nt], ah[mt], bb[nt >> 1][(nt & 1) * 2], bb[nt >> 1][(nt & 1) * 2 + 1]);
        }

        // convert next chunk's A between MMA halves (hides LDG latency, caps reg life)
        if (more) convert_chunk(smem, OFF_A + (s ^ 1) * A_STG, va, Ww, (c + 1) * KC, tid, aacc);

        // second half: ks 0..3 of plane 1
        #pragma unroll
        for (int ks = 0; ks < 4; ++ks) {
            uint32_t ah[2][4], bb[4][4];
            #pragma unroll
            for (int mt = 0; mt < 2; ++mt) {
                int row = arow_lane + mt * 16;
                uint32_t u = (uint32_t)((ks * 2 + a_uhalf) ^ (row & 7));
                LDSM4(ah[mt], abase + A_PLANE + (unsigned)row * 128 + (u << 4));
            }
            #pragma unroll
            for (int p = 0; p < 4; ++p) {
                int n = b_nlane + p * 16;
                uint32_t u = (uint32_t)((ks * 2 + b_uhalf) ^ (n & 7));
                LDSM4(bb[p], bbase + B_PLANE + (unsigned)n * 128 + (u << 4));
            }
            #pragma unroll
            for (int mt = 0; mt < 2; ++mt)
                #pragma unroll
                for (int nt = 0; nt < 8; ++nt)
                    MMA16816(acc[mt][nt], ah[mt], bb[nt >> 1][(nt & 1) * 2], bb[nt >> 1][(nt & 1) * 2 + 1]);
        }

        if (more) CPWAIT0();
        __syncthreads();
    }

    // ---------------- epilogue ----------------
    // alpha: reduce over the 4 threads of each row
    aacc += __shfl_xor_sync(0xffffffffu, aacc, 1);
    aacc += __shfl_xor_sync(0xffffffffu, aacc, 2);
    if ((tid & 3) == 0) alps[tid >> 2] = aacc;

    // rowsum partials: silu + W2 over this warp's 64 cols
    {
        #pragma unroll
        for (int mt = 0; mt < 2; ++mt) {
            float p0 = 0.0f, p1 = 0.0f;
            #pragma unroll
            for (int nt = 0; nt < 8; ++nt) {
                int col = wn * 64 + nt * 8 + 2 * (lid & 3);
                float bA = b1s[col], bB = b1s[col + 1];
                float wA = w2s[col], wB = w2s[col + 1];
                p0 += silu_f(acc[mt][nt][0] + bA) * wA + silu_f(acc[mt][nt][1] + bB) * wB;
                p1 += silu_f(acc[mt][nt][2] + bA) * wA + silu_f(acc[mt][nt][3] + bB) * wB;
            }
            p0 += __shfl_xor_sync(0xffffffffu, p0, 1);
            p0 += __shfl_xor_sync(0xffffffffu, p0, 2);
            p1 += __shfl_xor_sync(0xffffffffu, p1, 1);
            p1 += __shfl_xor_sync(0xffffffffu, p1, 2);
            if ((lid & 3) == 0) {
                int r = wm * 32 + mt * 16 + (lid >> 2);
                atomicAdd(&rsum[r], p0);
                atomicAdd(&rsum[r + 8], p1);
            }
        }
    }
    __syncthreads();

    // final: gate + segment sum
    if (tid < 128) {
        const int row = tid, grow = row0 + row;
        const bool valid = grow < N_ROWS;
        const float b2v = __ldg(b2), bwv = __ldg(bw);
        float val = valid ? (rsum[row] + b2v) * (alps[row] + bwv) : 0.0f;
        int g = valid
            ? (is64 ? (int)((const long long*)batch_raw)[grow] : ((const int*)batch_raw)[grow])
            : -1;
        float tot = 0.0f;
        #pragma unroll
        for (int k2 = 0; k2 < 32; ++k2) {
            float vk = __shfl_sync(0xffffffffu, val, k2);
            int   gk = __shfl_sync(0xffffffffu, g, k2);
            if (gk == g) tot += vk;
        }
        int gp = __shfl_up_sync(0xffffffffu, g, 1);
        if (valid && (lid == 0 || g != gp)) atomicAdd(out + g, tot);
    }
}

// ---------------- launch ----------------
extern "C" void kernel_launch(void* const* d_in, const int* in_sizes, int n_in,
                              void* d_out, int out_size) {
    const float* h     = (const float*)d_in[0];
    const void*  batch = d_in[3];
    const float* W1    = (const float*)d_in[5];
    const float* b1    = (const float*)d_in[6];
    const float* W2    = (const float*)d_in[7];
    const float* b2    = (const float*)d_in[8];
    const float* Ww    = (const float*)d_in[9];
    const float* bw    = (const float*)d_in[10];
    float* out = (float*)d_out;

    cudaFuncSetAttribute(fused_mma_kernel,
                         cudaFuncAttributeMaxDynamicSharedMemorySize, SMEM_TOTAL);

    prep_kernel<<<(HHALF * HID) / 256, 256>>>(W1, out);

    int grid = (N_ROWS + MROWS - 1) / MROWS;   // 1563
    fused_mma_kernel<<<grid, NTHREADS, SMEM_TOTAL>>>(h, batch, b1, W2, b2, Ww, bw, out);
}

// round 7
// speedup vs baseline: 1.9606x; 1.5500x over previous
#include <cuda_runtime.h>
#include <cuda_fp16.h>
#include <cstdint>

#define N_ROWS 200000
#define HID    512
#define HHALF  256
#define NG     2000
#define MROWS  64
#define KC     64
#define NCHUNK 8
#define NTHREADS 256

// smem byte offsets (per CTA)
#define OFF_B1    0
#define OFF_W2    1024
#define OFF_ALPHA 2048      // 64 floats
#define OFF_RSUM  2304      // 64 floats
#define OFF_A     2560      // 2 stages x 8KB
#define A_STG     8192
#define OFF_B     18944     // 2 stages x 32KB
#define B_STG     32768
#define SMEM_TOTAL 84480

__device__ __half g_W1h[HHALF * HID];

// ---------------- helpers ----------------
__device__ __forceinline__ uint32_t smem_u32(const void* p) {
    uint32_t a;
    asm("{ .reg .u64 t; cvta.to.shared.u64 t, %1; cvt.u32.u64 %0, t; }" : "=r"(a) : "l"(p));
    return a;
}
#define LDSM4(r, a) asm volatile("ldmatrix.sync.aligned.m8n8.x4.shared.b16 {%0,%1,%2,%3}, [%4];" \
    : "=r"((r)[0]),"=r"((r)[1]),"=r"((r)[2]),"=r"((r)[3]) : "r"(a))
#define MMA16816(d, a, b0, b1) asm volatile( \
    "mma.sync.aligned.m16n8k16.row.col.f32.f16.f16.f32 " \
    "{%0,%1,%2,%3}, {%4,%5,%6,%7}, {%8,%9}, {%0,%1,%2,%3};" \
    : "+f"((d)[0]),"+f"((d)[1]),"+f"((d)[2]),"+f"((d)[3]) \
    : "r"((a)[0]),"r"((a)[1]),"r"((a)[2]),"r"((a)[3]), "r"(b0),"r"(b1))
#define CPASYNC16(dst, src) asm volatile("cp.async.cg.shared.global [%0], [%1], 16;" :: "r"(dst), "l"(src) : "memory")
#define CPCOMMIT() asm volatile("cp.async.commit_group;" ::: "memory")
#define CPWAIT0()  asm volatile("cp.async.wait_group 0;" ::: "memory")

__device__ __forceinline__ uint32_t pack_f16x2(float e_lo, float e_hi) {
    uint32_t r;
    asm("cvt.rn.f16x2.f32 %0, %1, %2;" : "=r"(r) : "f"(e_hi), "f"(e_lo));
    return r;
}
__device__ __forceinline__ float silu_f(float z) { return __fdividef(z, 1.0f + __expf(-z)); }

// ---------------- prep kernel ----------------
__global__ void prep_kernel(const float* __restrict__ W1, float* __restrict__ out) {
    int i = blockIdx.x * blockDim.x + threadIdx.x;
    if (i < NG) out[i] = 0.0f;
    if (i < HHALF * HID) g_W1h[i] = __float2half(W1[i]);
}

// ---------------- device helpers ----------------
__device__ __forceinline__ void stage_B(uint32_t sbase, int st, int kk, int tid) {
    // 256 rows x 64 fp16 (128B/row), 2048 x 16B ops over 256 threads
    #pragma unroll
    for (int j = 0; j < 8; ++j) {
        int task = tid + j * 256;   // 0..2047
        int n    = task >> 3;
        int unit = task & 7;
        const __half* src = g_W1h + n * HID + kk + unit * 8;
        uint32_t dst = sbase + OFF_B + st * B_STG + n * 128
                     + (((unsigned)(unit ^ (n & 7))) << 4);
        CPASYNC16(dst, src);
    }
    CPCOMMIT();
}

__device__ __forceinline__ void load_va(float4 va[4], const float* __restrict__ h,
                                        int row0, int tid, int kk) {
    const int arow = tid >> 2;      // 0..63
    const int q    = tid & 3;       // k-slice of 16
    const float* p = h + (size_t)(row0 + arow) * HID + kk + q * 16;
    #pragma unroll
    for (int i = 0; i < 4; ++i) va[i] = __ldg((const float4*)(p + i * 4));
}

__device__ __forceinline__ void convert_chunk(char* smem, uint32_t abytes,
                                              const float4 va[4],
                                              const float* __restrict__ Ww,
                                              int kk, int tid, float& aacc) {
    const int arow = tid >> 2;
    const int q    = tid & 3;
    float a = 0.0f;
    #pragma unroll
    for (int i = 0; i < 4; ++i) {
        float4 w = __ldg((const float4*)(Ww + kk + q * 16 + i * 4));
        float4 v = va[i];
        a = fmaf(v.x, w.x, fmaf(v.y, w.y, fmaf(v.z, w.z, fmaf(v.w, w.w, a))));
    }
    aacc += a;
    #pragma unroll
    for (int p = 0; p < 2; ++p) {
        float4 v0 = va[2 * p], v1 = va[2 * p + 1];
        uint4 pk = make_uint4(pack_f16x2(v0.x, v0.y), pack_f16x2(v0.z, v0.w),
                              pack_f16x2(v1.x, v1.y), pack_f16x2(v1.z, v1.w));
        uint32_t u = (unsigned)(q * 2 + p);
        uint32_t off = (unsigned)arow * 128 + (((u ^ (arow & 7))) << 4);
        *(uint4*)(smem + abytes + off) = pk;
    }
}

// ---------------- main kernel ----------------
__global__ __launch_bounds__(NTHREADS, 2)
void fused_mma_kernel(
    const float* __restrict__ h,
    const void*  __restrict__ batch_raw,
    const float* __restrict__ b1,
    const float* __restrict__ W2,
    const float* __restrict__ b2,
    const float* __restrict__ Ww,
    const float* __restrict__ bw,
    float* __restrict__ out)
{
    extern __shared__ char smem[];
    const uint32_t sbase = smem_u32(smem);
    const int tid = threadIdx.x;
    const int wid = tid >> 5, lid = tid & 31;
    const int row0 = blockIdx.x * MROWS;

    float* b1s  = (float*)(smem + OFF_B1);
    float* w2s  = (float*)(smem + OFF_W2);
    float* alps = (float*)(smem + OFF_ALPHA);
    float* rsum = (float*)(smem + OFF_RSUM);

    b1s[tid] = b1[tid];
    w2s[tid] = W2[tid];
    if (tid < MROWS) rsum[tid] = 0.0f;

    const bool is64 = (((const int*)batch_raw)[N_ROWS - 1] == 0);

    // warp layout: 2 x 4 grid of 32x64 tiles
    const int wm = wid >> 2;          // 0..1
    const int wn = wid & 3;           // 0..3
    const int arow_lane = wm * 32 + (lid & 15);
    const int a_uhalf   = lid >> 4;
    const int b_nlane   = wn * 64 + (lid & 7) + ((lid >> 4) << 3);
    const int b_uhalf   = (lid >> 3) & 1;

    float acc[2][8][4];
    #pragma unroll
    for (int a = 0; a < 2; ++a)
        #pragma unroll
        for (int b = 0; b < 8; ++b)
            #pragma unroll
            for (int c = 0; c < 4; ++c) acc[a][b][c] = 0.0f;

    float aacc = 0.0f;
    float4 va[4];

    // ---------------- prologue ----------------
    stage_B(sbase, 0, 0, tid);
    load_va(va, h, row0, tid, 0);
    convert_chunk(smem, OFF_A, va, Ww, 0, tid, aacc);
    CPWAIT0();
    __syncthreads();

    // ---------------- main loop ----------------
    for (int c = 0; c < NCHUNK; ++c) {
        const int s = c & 1;
        const bool more = (c + 1) < NCHUNK;
        if (more) {
            stage_B(sbase, s ^ 1, (c + 1) * KC, tid);
            load_va(va, h, row0, tid, (c + 1) * KC);
        }

        const uint32_t abase = sbase + OFF_A + s * A_STG;
        const uint32_t bbase = sbase + OFF_B + s * B_STG;

        // first half: ks 0..1
        #pragma unroll
        for (int ks = 0; ks < 2; ++ks) {
            uint32_t ah[2][4], bb[4][4];
            #pragma unroll
            for (int mt = 0; mt < 2; ++mt) {
                int row = arow_lane + mt * 16;
                uint32_t u = (uint32_t)((ks * 2 + a_uhalf) ^ (row & 7));
                LDSM4(ah[mt], abase + (unsigned)row * 128 + (u << 4));
            }
            #pragma unroll
            for (int p = 0; p < 4; ++p) {
                int n = b_nlane + p * 16;
                uint32_t u = (uint32_t)((ks * 2 + b_uhalf) ^ (n & 7));
                LDSM4(bb[p], bbase + (unsigned)n * 128 + (u << 4));
            }
            #pragma unroll
            for (int mt = 0; mt < 2; ++mt)
                #pragma unroll
                for (int nt = 0; nt < 8; ++nt)
                    MMA16816(acc[mt][nt], ah[mt], bb[nt >> 1][(nt & 1) * 2], bb[nt >> 1][(nt & 1) * 2 + 1]);
        }

        // convert next chunk's A mid-chunk (overlaps LDG latency)
        if (more) convert_chunk(smem, OFF_A + (s ^ 1) * A_STG, va, Ww, (c + 1) * KC, tid, aacc);

        // second half: ks 2..3
        #pragma unroll
        for (int ks = 2; ks < 4; ++ks) {
            uint32_t ah[2][4], bb[4][4];
            #pragma unroll
            for (int mt = 0; mt < 2; ++mt) {
                int row = arow_lane + mt * 16;
                uint32_t u = (uint32_t)((ks * 2 + a_uhalf) ^ (row & 7));
                LDSM4(ah[mt], abase + (unsigned)row * 128 + (u << 4));
            }
            #pragma unroll
            for (int p = 0; p < 4; ++p) {
                int n = b_nlane + p * 16;
                uint32_t u = (uint32_t)((ks * 2 + b_uhalf) ^ (n & 7));
                LDSM4(bb[p], bbase + (unsigned)n * 128 + (u << 4));
            }
            #pragma unroll
            for (int mt = 0; mt < 2; ++mt)
                #pragma unroll
                for (int nt = 0; nt < 8; ++nt)
                    MMA16816(acc[mt][nt], ah[mt], bb[nt >> 1][(nt & 1) * 2], bb[nt >> 1][(nt & 1) * 2 + 1]);
        }

        if (more) CPWAIT0();
        __syncthreads();
    }

    // ---------------- epilogue ----------------
    // alpha: reduce the 4 k-slice threads of each row (adjacent lanes)
    aacc += __shfl_xor_sync(0xffffffffu, aacc, 1);
    aacc += __shfl_xor_sync(0xffffffffu, aacc, 2);
    if ((tid & 3) == 0) alps[tid >> 2] = aacc;

    // rowsum partials: silu + W2 over this warp's 64 cols
    {
        #pragma unroll
        for (int mt = 0; mt < 2; ++mt) {
            float p0 = 0.0f, p1 = 0.0f;
            #pragma unroll
            for (int nt = 0; nt < 8; ++nt) {
                int col = wn * 64 + nt * 8 + 2 * (lid & 3);
                float bA = b1s[col], bB = b1s[col + 1];
                float wA = w2s[col], wB = w2s[col + 1];
                p0 += silu_f(acc[mt][nt][0] + bA) * wA + silu_f(acc[mt][nt][1] + bB) * wB;
                p1 += silu_f(acc[mt][nt][2] + bA) * wA + silu_f(acc[mt][nt][3] + bB) * wB;
            }
            p0 += __shfl_xor_sync(0xffffffffu, p0, 1);
            p0 += __shfl_xor_sync(0xffffffffu, p0, 2);
            p1 += __shfl_xor_sync(0xffffffffu, p1, 1);
            p1 += __shfl_xor_sync(0xffffffffu, p1, 2);
            if ((lid & 3) == 0) {
                int r = wm * 32 + mt * 16 + (lid >> 2);
                atomicAdd(&rsum[r], p0);
                atomicAdd(&rsum[r + 8], p1);
            }
        }
    }
    __syncthreads();

    // final: gate + segment sum (2 warps)
    if (tid < MROWS) {
        const int row = tid, grow = row0 + row;
        const float b2v = __ldg(b2), bwv = __ldg(bw);
        float val = (rsum[row] + b2v) * (alps[row] + bwv);
        int g = is64 ? (int)((const long long*)batch_raw)[grow]
                     : ((const int*)batch_raw)[grow];
        float tot = 0.0f;
        #pragma unroll
        for (int k2 = 0; k2 < 32; ++k2) {
            float vk = __shfl_sync(0xffffffffu, val, k2);
            int   gk = __shfl_sync(0xffffffffu, g, k2);
            if (gk == g) tot += vk;
        }
        int gp = __shfl_up_sync(0xffffffffu, g, 1);
        if (lid == 0 || g != gp) atomicAdd(out + g, tot);
    }
}

// ---------------- launch ----------------
extern "C" void kernel_launch(void* const* d_in, const int* in_sizes, int n_in,
                              void* d_out, int out_size) {
    const float* h     = (const float*)d_in[0];
    const void*  batch = d_in[3];
    const float* W1    = (const float*)d_in[5];
    const float* b1    = (const float*)d_in[6];
    const float* W2    = (const float*)d_in[7];
    const float* b2    = (const float*)d_in[8];
    const float* Ww    = (const float*)d_in[9];
    const float* bw    = (const float*)d_in[10];
    float* out = (float*)d_out;

    cudaFuncSetAttribute(fused_mma_kernel,
                         cudaFuncAttributeMaxDynamicSharedMemorySize, SMEM_TOTAL);

    prep_kernel<<<(HHALF * HID) / 256, 256>>>(W1, out);

    int grid = N_ROWS / MROWS;   // 3125, exact
    fused_mma_kernel<<<grid, NTHREADS, SMEM_TOTAL>>>(h, batch, b1, W2, b2, Ww, bw, out);
}

// round 8
// speedup vs baseline: 2.2859x; 1.1659x over previous
#include <cuda_runtime.h>
#include <cuda_fp16.h>
#include <cstdint>

#define N_ROWS 200000
#define HID    512
#define HHALF  256
#define NG     2000
#define MROWS  64
#define KC32   32
#define NCH    16
#define NTHREADS 256

// smem byte offsets (per CTA)
#define OFF_ALPHA 0          // 64 floats
#define OFF_RSUM  256        // 64 floats
#define OFF_A     1024       // 2 stages x 5120B (64 rows x 80B)
#define A_STG     5120
#define OFF_H     11264      // 4 stages x 8192B (64 rows x 128B fp32, swizzled)
#define H_STG     8192
#define OFF_B     44032      // 2 stages x 32768B (256 rows x 128B fp16, swizzled)
#define B_STG     32768
#define SMEM_TOTAL 109568

__device__ __half g_W1h[HHALF * HID];

// ---------------- helpers ----------------
__device__ __forceinline__ uint32_t smem_u32(const void* p) {
    uint32_t a;
    asm("{ .reg .u64 t; cvta.to.shared.u64 t, %1; cvt.u32.u64 %0, t; }" : "=r"(a) : "l"(p));
    return a;
}
#define LDSM4(r, a) asm volatile("ldmatrix.sync.aligned.m8n8.x4.shared.b16 {%0,%1,%2,%3}, [%4];" \
    : "=r"((r)[0]),"=r"((r)[1]),"=r"((r)[2]),"=r"((r)[3]) : "r"(a))
#define MMA16816(d, a, b0, b1) asm volatile( \
    "mma.sync.aligned.m16n8k16.row.col.f32.f16.f16.f32 " \
    "{%0,%1,%2,%3}, {%4,%5,%6,%7}, {%8,%9}, {%0,%1,%2,%3};" \
    : "+f"((d)[0]),"+f"((d)[1]),"+f"((d)[2]),"+f"((d)[3]) \
    : "r"((a)[0]),"r"((a)[1]),"r"((a)[2]),"r"((a)[3]), "r"(b0),"r"(b1))
#define CPASYNC16(dst, src) asm volatile("cp.async.cg.shared.global [%0], [%1], 16;" :: "r"(dst), "l"(src) : "memory")
#define CPCOMMIT() asm volatile("cp.async.commit_group;" ::: "memory")
#define CPWAIT0()  asm volatile("cp.async.wait_group 0;" ::: "memory")
#define CPWAIT1()  asm volatile("cp.async.wait_group 1;" ::: "memory")

__device__ __forceinline__ uint32_t pack_f16x2(float e_lo, float e_hi) {
    uint32_t r;
    asm("cvt.rn.f16x2.f32 %0, %1, %2;" : "=r"(r) : "f"(e_hi), "f"(e_lo));
    return r;
}
__device__ __forceinline__ float silu_f(float z) { return __fdividef(z, 1.0f + __expf(-z)); }

// ---------------- prep kernel ----------------
__global__ void prep_kernel(const float* __restrict__ W1, float* __restrict__ out) {
    int i = blockIdx.x * blockDim.x + threadIdx.x;
    if (i < NG) out[i] = 0.0f;
    if (i < HHALF * HID) g_W1h[i] = __float2half(W1[i]);
}

// ---------------- staging ----------------
// h chunk: 64 rows x 32 fp32 (128B/row), XOR-swizzled, 512 x 16B tasks
__device__ __forceinline__ void stage_h(uint32_t sbase, int st, int kk,
                                        const float* __restrict__ h, int row0, int tid) {
    #pragma unroll
    for (int j = 0; j < 2; ++j) {
        int task = tid + j * 256;
        int row  = task >> 3;
        int unit = task & 7;
        const float* src = h + (size_t)(row0 + row) * HID + kk + unit * 4;
        uint32_t dst = sbase + OFF_H + st * H_STG + row * 128
                     + (((unsigned)(unit ^ (row & 7))) << 4);
        CPASYNC16(dst, src);
    }
}

// B pair: 256 rows x 64 fp16 (128B/row), XOR-swizzled, 2048 x 16B tasks
__device__ __forceinline__ void stage_B(uint32_t sbase, int st, int kk, int tid) {
    #pragma unroll
    for (int j = 0; j < 8; ++j) {
        int task = tid + j * 256;
        int n    = task >> 3;
        int unit = task & 7;
        const __half* src = g_W1h + n * HID + kk + unit * 8;
        uint32_t dst = sbase + OFF_B + st * B_STG + n * 128
                     + (((unsigned)(unit ^ (n & 7))) << 4);
        CPASYNC16(dst, src);
    }
}

// convert h fp32 smem (stage chunk&3) -> A fp16 smem (stage chunk&1) + alpha partial
__device__ __forceinline__ void convert_chunk(char* smem, int chunk,
                                              const float* __restrict__ Ww,
                                              int tid, float& aacc) {
    const int arow = tid >> 2;
    const int q    = tid & 3;
    const char* hb = smem + OFF_H + (chunk & 3) * H_STG + arow * 128;
    uint32_t u0 = (unsigned)((2 * q)     ^ (arow & 7));
    uint32_t u1 = (unsigned)((2 * q + 1) ^ (arow & 7));
    float4 v0 = *(const float4*)(hb + (u0 << 4));
    float4 v1 = *(const float4*)(hb + (u1 << 4));
    float4 w0 = __ldg((const float4*)(Ww + chunk * KC32 + q * 8));
    float4 w1 = __ldg((const float4*)(Ww + chunk * KC32 + q * 8 + 4));
    aacc += v0.x * w0.x + v0.y * w0.y + v0.z * w0.z + v0.w * w0.w
          + v1.x * w1.x + v1.y * w1.y + v1.z * w1.z + v1.w * w1.w;
    uint4 pk = make_uint4(pack_f16x2(v0.x, v0.y), pack_f16x2(v0.z, v0.w),
                          pack_f16x2(v1.x, v1.y), pack_f16x2(v1.z, v1.w));
    *(uint4*)(smem + OFF_A + (chunk & 1) * A_STG + arow * 80 + q * 16) = pk;
}

// ---------------- main kernel ----------------
__global__ __launch_bounds__(NTHREADS, 2)
void fused_mma_kernel(
    const float* __restrict__ h,
    const void*  __restrict__ batch_raw,
    const float* __restrict__ b1,
    const float* __restrict__ W2,
    const float* __restrict__ b2,
    const float* __restrict__ Ww,
    const float* __restrict__ bw,
    float* __restrict__ out)
{
    extern __shared__ char smem[];
    const uint32_t sbase = smem_u32(smem);
    const int tid = threadIdx.x;
    const int wid = tid >> 5, lid = tid & 31;
    const int row0 = blockIdx.x * MROWS;

    float* alps = (float*)(smem + OFF_ALPHA);
    float* rsum = (float*)(smem + OFF_RSUM);
    if (tid < MROWS) rsum[tid] = 0.0f;

    const bool is64 = (((const int*)batch_raw)[N_ROWS - 1] == 0);

    // warp layout: 2 x 4 grid of 32x64 tiles
    const int wm = wid >> 2;
    const int wn = wid & 3;
    const int arow_lane = wm * 32 + (lid & 15);
    const int a_klane   = (lid >> 4) * 16;      // k-half byte offset within 32B
    const int b_nlane   = wn * 64 + (lid & 7) + ((lid >> 4) << 3);
    const int b_uhalf   = (lid >> 3) & 1;

    float acc[2][8][4];
    #pragma unroll
    for (int a = 0; a < 2; ++a)
        #pragma unroll
        for (int b = 0; b < 8; ++b)
            #pragma unroll
            for (int c = 0; c < 4; ++c) acc[a][b][c] = 0.0f;

    float aacc = 0.0f;

    // ---------------- prologue ----------------
    stage_h(sbase, 0, 0, h, row0, tid);
    stage_B(sbase, 0, 0, tid);
    CPCOMMIT();
    stage_h(sbase, 1, KC32, h, row0, tid);
    CPCOMMIT();
    stage_h(sbase, 2, 2 * KC32, h, row0, tid);
    stage_B(sbase, 1, 64, tid);
    CPCOMMIT();
    CPWAIT0();
    __syncthreads();
    convert_chunk(smem, 0, Ww, tid, aacc);
    __syncthreads();

    // ---------------- main loop (16 chunks of K=32) ----------------
    for (int c = 0; c < NCH; ++c) {
        // top: issue next loads, exactly one commit group per chunk
        if (c + 3 < NCH) stage_h(sbase, (c + 3) & 3, (c + 3) * KC32, h, row0, tid);
        if ((c & 1) == 0 && c + 2 < NCH)
            stage_B(sbase, ((c >> 1) + 1) & 1, (c + 2) * KC32, tid);
        CPCOMMIT();

        const uint32_t abase = sbase + OFF_A + (c & 1) * A_STG;
        const uint32_t bbase = sbase + OFF_B + ((c >> 1) & 1) * B_STG;
        const int khalf = c & 1;

        // ks = 0
        {
            uint32_t ah[2][4], bb[4][4];
            #pragma unroll
            for (int mt = 0; mt < 2; ++mt) {
                int row = arow_lane + mt * 16;
                LDSM4(ah[mt], abase + (unsigned)row * 80 + a_klane);
            }
            #pragma unroll
            for (int p = 0; p < 4; ++p) {
                int n = b_nlane + p * 16;
                uint32_t u = (uint32_t)((khalf * 4 + b_uhalf) ^ (n & 7));
                LDSM4(bb[p], bbase + (unsigned)n * 128 + (u << 4));
            }
            #pragma unroll
            for (int mt = 0; mt < 2; ++mt)
                #pragma unroll
                for (int nt = 0; nt < 8; ++nt)
                    MMA16816(acc[mt][nt], ah[mt], bb[nt >> 1][(nt & 1) * 2], bb[nt >> 1][(nt & 1) * 2 + 1]);
        }

        // convert next chunk mid-chunk (h arrived; visibility via prior sync)
        if (c + 1 < NCH) convert_chunk(smem, c + 1, Ww, tid, aacc);

        // ks = 1
        {
            uint32_t ah[2][4], bb[4][4];
            #pragma unroll
            for (int mt = 0; mt < 2; ++mt) {
                int row = arow_lane + mt * 16;
                LDSM4(ah[mt], abase + (unsigned)row * 80 + 32 + a_klane);
            }
            #pragma unroll
            for (int p = 0; p < 4; ++p) {
                int n = b_nlane + p * 16;
                uint32_t u = (uint32_t)((khalf * 4 + 2 + b_uhalf) ^ (n & 7));
                LDSM4(bb[p], bbase + (unsigned)n * 128 + (u << 4));
            }
            #pragma unroll
            for (int mt = 0; mt < 2; ++mt)
                #pragma unroll
                for (int nt = 0; nt < 8; ++nt)
                    MMA16816(acc[mt][nt], ah[mt], bb[nt >> 1][(nt & 1) * 2], bb[nt >> 1][(nt & 1) * 2 + 1]);
        }

        CPWAIT1();          // h(c+1) (committed at c-2) + B next pair guaranteed in
        __syncthreads();
    }

    // ---------------- epilogue ----------------
    // alpha: reduce the 4 k-slice threads of each row
    aacc += __shfl_xor_sync(0xffffffffu, aacc, 1);
    aacc += __shfl_xor_sync(0xffffffffu, aacc, 2);
    if ((tid & 3) == 0) alps[tid >> 2] = aacc;

    // rowsum partials: silu + W2 over this warp's 64 cols
    {
        #pragma unroll
        for (int mt = 0; mt < 2; ++mt) {
            float p0 = 0.0f, p1 = 0.0f;
            #pragma unroll
            for (int nt = 0; nt < 8; ++nt) {
                int col = wn * 64 + nt * 8 + 2 * (lid & 3);
                float bA = __ldg(b1 + col), bB = __ldg(b1 + col + 1);
                float wA = __ldg(W2 + col), wB = __ldg(W2 + col + 1);
                p0 += silu_f(acc[mt][nt][0] + bA) * wA + silu_f(acc[mt][nt][1] + bB) * wB;
                p1 += silu_f(acc[mt][nt][2] + bA) * wA + silu_f(acc[mt][nt][3] + bB) * wB;
            }
            p0 += __shfl_xor_sync(0xffffffffu, p0, 1);
            p0 += __shfl_xor_sync(0xffffffffu, p0, 2);
            p1 += __shfl_xor_sync(0xffffffffu, p1, 1);
            p1 += __shfl_xor_sync(0xffffffffu, p1, 2);
            if ((lid & 3) == 0) {
                int r = wm * 32 + mt * 16 + (lid >> 2);
                atomicAdd(&rsum[r], p0);
                atomicAdd(&rsum[r + 8], p1);
            }
        }
    }
    __syncthreads();

    // final: gate + segment sum
    if (tid < MROWS) {
        const int row = tid, grow = row0 + row;
        const float b2v = __ldg(b2), bwv = __ldg(bw);
        float val = (rsum[row] + b2v) * (alps[row] + bwv);
        int g = is64 ? (int)((const long long*)batch_raw)[grow]
                     : ((const int*)batch_raw)[grow];
        float tot = 0.0f;
        #pragma unroll
        for (int k2 = 0; k2 < 32; ++k2) {
            float vk = __shfl_sync(0xffffffffu, val, k2);
            int   gk = __shfl_sync(0xffffffffu, g, k2);
            if (gk == g) tot += vk;
        }
        int gp = __shfl_up_sync(0xffffffffu, g, 1);
        if (lid == 0 || g != gp) atomicAdd(out + g, tot);
    }
}

// ---------------- launch ----------------
extern "C" void kernel_launch(void* const* d_in, const int* in_sizes, int n_in,
                              void* d_out, int out_size) {
    const float* h     = (const float*)d_in[0];
    const void*  batch = d_in[3];
    const float* W1    = (const float*)d_in[5];
    const float* b1    = (const float*)d_in[6];
    const float* W2    = (const float*)d_in[7];
    const float* b2    = (const float*)d_in[8];
    const float* Ww    = (const float*)d_in[9];
    const float* bw    = (const float*)d_in[10];
    float* out = (float*)d_out;

    cudaFuncSetAttribute(fused_mma_kernel,
                         cudaFuncAttributeMaxDynamicSharedMemorySize, SMEM_TOTAL);

    prep_kernel<<<(HHALF * HID) / 256, 256>>>(W1, out);

    int grid = N_ROWS / MROWS;   // 3125, exact
    fused_mma_kernel<<<grid, NTHREADS, SMEM_TOTAL>>>(h, batch, b1, W2, b2, Ww, bw, out);
}

// round 9
// speedup vs baseline: 2.5217x; 1.1032x over previous
#include <cuda_runtime.h>
#include <cuda_fp16.h>
#include <cstdint>

#define N_ROWS 200000
#define HID    512
#define HHALF  256
#define NG     2000
#define MROWS  64
#define NTHREADS 256

// smem layout (per CTA)
#define OFF_ALPHA 0          // 64 floats
#define OFF_RSUM  256        // 64 floats
#define OFF_A     1024       // 4 stages x 4096B (paired-row swizzled fp16, K=32)
#define A_STG     4096
#define OFF_H     17408      // 4 stages x 8192B (64 rows x 128B fp32, swizzled, K=32)
#define H_STG     8192
#define OFF_B     50176      // 2 stages x 32768B (256 rows x 128B fp16, K=64 pair)
#define B_STG     32768
#define SMEM_TOTAL 115712

__device__ __half g_W1h[HHALF * HID];

// ---------------- helpers ----------------
__device__ __forceinline__ uint32_t smem_u32(const void* p) {
    uint32_t a;
    asm("{ .reg .u64 t; cvta.to.shared.u64 t, %1; cvt.u32.u64 %0, t; }" : "=r"(a) : "l"(p));
    return a;
}
#define LDSM4(r, a) asm volatile("ldmatrix.sync.aligned.m8n8.x4.shared.b16 {%0,%1,%2,%3}, [%4];" \
    : "=r"((r)[0]),"=r"((r)[1]),"=r"((r)[2]),"=r"((r)[3]) : "r"(a))
#define MMA16816(d, a, b0, b1) asm volatile( \
    "mma.sync.aligned.m16n8k16.row.col.f32.f16.f16.f32 " \
    "{%0,%1,%2,%3}, {%4,%5,%6,%7}, {%8,%9}, {%0,%1,%2,%3};" \
    : "+f"((d)[0]),"+f"((d)[1]),"+f"((d)[2]),"+f"((d)[3]) \
    : "r"((a)[0]),"r"((a)[1]),"r"((a)[2]),"r"((a)[3]), "r"(b0),"r"(b1))
#define CPASYNC16(dst, src) asm volatile("cp.async.cg.shared.global [%0], [%1], 16;" :: "r"(dst), "l"(src) : "memory")
#define CPCOMMIT() asm volatile("cp.async.commit_group;" ::: "memory")
#define CPWAIT0()  asm volatile("cp.async.wait_group 0;" ::: "memory")

__device__ __forceinline__ uint32_t pack_f16x2(float e_lo, float e_hi) {
    uint32_t r;
    asm("cvt.rn.f16x2.f32 %0, %1, %2;" : "=r"(r) : "f"(e_hi), "f"(e_lo));
    return r;
}
__device__ __forceinline__ float silu_f(float z) { return __fdividef(z, 1.0f + __expf(-z)); }

// ---------------- prep kernel ----------------
__global__ void prep_kernel(const float* __restrict__ W1, float* __restrict__ out) {
    int i = blockIdx.x * blockDim.x + threadIdx.x;
    if (i < NG) out[i] = 0.0f;
    if (i < HHALF * HID) g_W1h[i] = __float2half(W1[i]);
}

// ---------------- staging ----------------
// h chunk (K=32): 64 rows x 128B fp32, XOR-swizzled
__device__ __forceinline__ void stage_h(uint32_t sbase, int st, int kk,
                                        const float* __restrict__ h, int row0, int tid) {
    #pragma unroll
    for (int j = 0; j < 2; ++j) {
        int task = tid + j * 256;
        int row  = task >> 3;
        int unit = task & 7;
        const float* src = h + (size_t)(row0 + row) * HID + kk + unit * 4;
        uint32_t dst = sbase + OFF_H + st * H_STG + row * 128
                     + (((unsigned)(unit ^ (row & 7))) << 4);
        CPASYNC16(dst, src);
    }
}

// B pair (K=64): 256 rows x 128B fp16, XOR-swizzled
__device__ __forceinline__ void stage_B(uint32_t sbase, int st, int kk, int tid) {
    #pragma unroll
    for (int j = 0; j < 8; ++j) {
        int task = tid + j * 256;
        int n    = task >> 3;
        int unit = task & 7;
        const __half* src = g_W1h + n * HID + kk + unit * 8;
        uint32_t dst = sbase + OFF_B + st * B_STG + n * 128
                     + (((unsigned)(unit ^ (n & 7))) << 4);
        CPASYNC16(dst, src);
    }
}

// convert h fp32 (stage chunk&3) -> A fp16 (stage chunk&3, paired-row layout) + alpha partial
__device__ __forceinline__ void convert_chunk(char* smem, int chunk,
                                              const float* __restrict__ Ww,
                                              int tid, float& aacc) {
    const int ar = tid >> 2;
    const int q  = tid & 3;
    const char* hb = smem + OFF_H + (chunk & 3) * H_STG + ar * 128;
    uint32_t u0 = (unsigned)((2 * q)     ^ (ar & 7));
    uint32_t u1 = (unsigned)((2 * q + 1) ^ (ar & 7));
    float4 v0 = *(const float4*)(hb + (u0 << 4));
    float4 v1 = *(const float4*)(hb + (u1 << 4));
    float4 w0 = __ldg((const float4*)(Ww + chunk * 32 + q * 8));
    float4 w1 = __ldg((const float4*)(Ww + chunk * 32 + q * 8 + 4));
    aacc += v0.x * w0.x + v0.y * w0.y + v0.z * w0.z + v0.w * w0.w
          + v1.x * w1.x + v1.y * w1.y + v1.z * w1.z + v1.w * w1.w;
    uint4 pk = make_uint4(pack_f16x2(v0.x, v0.y), pack_f16x2(v0.z, v0.w),
                          pack_f16x2(v1.x, v1.y), pack_f16x2(v1.z, v1.w));
    // paired-row A: physical row ar>>1 (128B), unit index 4*(ar&1)+q, swizzle ^((ar>>1)&7)
    uint32_t dst = OFF_A + (chunk & 3) * A_STG + (ar >> 1) * 128
                 + ((unsigned)(((4 * (ar & 1) + q) ^ ((ar >> 1) & 7))) << 4);
    *(uint4*)(smem + dst) = pk;
}

// ---------------- main kernel ----------------
__global__ __launch_bounds__(NTHREADS, 2)
void fused_mma_kernel(
    const float* __restrict__ h,
    const void*  __restrict__ batch_raw,
    const float* __restrict__ b1,
    const float* __restrict__ W2,
    const float* __restrict__ b2,
    const float* __restrict__ Ww,
    const float* __restrict__ bw,
    float* __restrict__ out)
{
    extern __shared__ char smem[];
    const uint32_t sbase = smem_u32(smem);
    const int tid = threadIdx.x;
    const int wid = tid >> 5, lid = tid & 31;
    const int row0 = blockIdx.x * MROWS;

    float* alps = (float*)(smem + OFF_ALPHA);
    float* rsum = (float*)(smem + OFF_RSUM);
    if (tid < MROWS) rsum[tid] = 0.0f;

    const bool is64 = (((const int*)batch_raw)[N_ROWS - 1] == 0);

    // warp layout: 2 x 4 grid of 32x64 tiles
    const int wm = wid >> 2;
    const int wn = wid & 3;
    const int arow_lane = wm * 32 + (lid & 15);
    const int a_uhalf   = lid >> 4;
    const int b_nlane   = wn * 64 + (lid & 7) + ((lid >> 4) << 3);
    const int b_uhalf   = (lid >> 3) & 1;

    float acc[2][8][4];
    #pragma unroll
    for (int a = 0; a < 2; ++a)
        #pragma unroll
        for (int b = 0; b < 8; ++b)
            #pragma unroll
            for (int c = 0; c < 4; ++c) acc[a][b][c] = 0.0f;

    float aacc = 0.0f;

// MMA over one K=32 chunk: A stage AST, B stage BST, k-half KH within B pair
#define MMA_CHUNK(AST, BST, KH)                                                     \
    {                                                                               \
        const uint32_t abase = sbase + OFF_A + (AST) * A_STG;                       \
        const uint32_t bbase = sbase + OFF_B + (BST) * B_STG;                       \
        _Pragma("unroll")                                                           \
        for (int ks = 0; ks < 2; ++ks) {                                            \
            uint32_t ah[2][4], bb[4][4];                                            \
            _Pragma("unroll")                                                       \
            for (int mt = 0; mt < 2; ++mt) {                                        \
                int r = arow_lane + mt * 16;                                        \
                uint32_t u = (uint32_t)((4 * (r & 1) + ks * 2 + a_uhalf)            \
                                        ^ ((r >> 1) & 7));                          \
                LDSM4(ah[mt], abase + (unsigned)(r >> 1) * 128 + (u << 4));         \
            }                                                                       \
            _Pragma("unroll")                                                       \
            for (int p = 0; p < 4; ++p) {                                           \
                int n = b_nlane + p * 16;                                           \
                uint32_t u = (uint32_t)(((KH) * 4 + ks * 2 + b_uhalf) ^ (n & 7));   \
                LDSM4(bb[p], bbase + (unsigned)n * 128 + (u << 4));                 \
            }                                                                       \
            _Pragma("unroll")                                                       \
            for (int mt = 0; mt < 2; ++mt)                                          \
                _Pragma("unroll")                                                   \
                for (int nt = 0; nt < 8; ++nt)                                      \
                    MMA16816(acc[mt][nt], ah[mt],                                   \
                             bb[nt >> 1][(nt & 1) * 2], bb[nt >> 1][(nt & 1) * 2 + 1]); \
        }                                                                           \
    }

    // ---------------- prologue: chunks 0-3 staged, 0-1 converted ----------------
    stage_h(sbase, 0, 0,  h, row0, tid);
    stage_h(sbase, 1, 32, h, row0, tid);
    stage_h(sbase, 2, 64, h, row0, tid);
    stage_h(sbase, 3, 96, h, row0, tid);
    stage_B(sbase, 0, 0, tid);
    CPCOMMIT();
    CPWAIT0();
    __syncthreads();
    convert_chunk(smem, 0, Ww, tid, aacc);
    convert_chunk(smem, 1, Ww, tid, aacc);
    __syncthreads();

    // ---------------- main loop: 8 iterations of 2 chunks ----------------
    for (int i = 0; i < 8; ++i) {
        const int c0 = 2 * i;
        if (i <= 5) {
            stage_h(sbase, (c0 + 4) & 3, (c0 + 4) * 32, h, row0, tid);
            stage_h(sbase, (c0 + 5) & 3, (c0 + 5) * 32, h, row0, tid);
        }
        if (i <= 6) stage_B(sbase, (i + 1) & 1, (i + 1) * 64, tid);
        CPCOMMIT();

        MMA_CHUNK(c0 & 3, i & 1, 0);
        if (i <= 6) convert_chunk(smem, c0 + 2, Ww, tid, aacc);
        MMA_CHUNK((c0 + 1) & 3, i & 1, 1);
        if (i <= 6) convert_chunk(smem, c0 + 3, Ww, tid, aacc);

        CPWAIT0();
        __syncthreads();
    }

    // ---------------- epilogue ----------------
    // alpha: reduce the 4 k-slice threads of each row
    aacc += __shfl_xor_sync(0xffffffffu, aacc, 1);
    aacc += __shfl_xor_sync(0xffffffffu, aacc, 2);
    if ((tid & 3) == 0) alps[tid >> 2] = aacc;

    // rowsum partials: silu + W2 over this warp's 64 cols
    {
        #pragma unroll
        for (int mt = 0; mt < 2; ++mt) {
            float p0 = 0.0f, p1 = 0.0f;
            #pragma unroll
            for (int nt = 0; nt < 8; ++nt) {
                int col = wn * 64 + nt * 8 + 2 * (lid & 3);
                float bA = __ldg(b1 + col), bB = __ldg(b1 + col + 1);
                float wA = __ldg(W2 + col), wB = __ldg(W2 + col + 1);
                p0 += silu_f(acc[mt][nt][0] + bA) * wA + silu_f(acc[mt][nt][1] + bB) * wB;
                p1 += silu_f(acc[mt][nt][2] + bA) * wA + silu_f(acc[mt][nt][3] + bB) * wB;
            }
            p0 += __shfl_xor_sync(0xffffffffu, p0, 1);
            p0 += __shfl_xor_sync(0xffffffffu, p0, 2);
            p1 += __shfl_xor_sync(0xffffffffu, p1, 1);
            p1 += __shfl_xor_sync(0xffffffffu, p1, 2);
            if ((lid & 3) == 0) {
                int r = wm * 32 + mt * 16 + (lid >> 2);
                atomicAdd(&rsum[r], p0);
                atomicAdd(&rsum[r + 8], p1);
            }
        }
    }
    __syncthreads();

    // final: gate + segment sum
    if (tid < MROWS) {
        const int row = tid, grow = row0 + row;
        const float b2v = __ldg(b2), bwv = __ldg(bw);
        float val = (rsum[row] + b2v) * (alps[row] + bwv);
        int g = is64 ? (int)((const long long*)batch_raw)[grow]
                     : ((const int*)batch_raw)[grow];
        float tot = 0.0f;
        #pragma unroll
        for (int k2 = 0; k2 < 32; ++k2) {
            float vk = __shfl_sync(0xffffffffu, val, k2);
            int   gk = __shfl_sync(0xffffffffu, g, k2);
            if (gk == g) tot += vk;
        }
        int gp = __shfl_up_sync(0xffffffffu, g, 1);
        if (lid == 0 || g != gp) atomicAdd(out + g, tot);
    }
#undef MMA_CHUNK
}

// ---------------- launch ----------------
extern "C" void kernel_launch(void* const* d_in, const int* in_sizes, int n_in,
                              void* d_out, int out_size) {
    const float* h     = (const float*)d_in[0];
    const void*  batch = d_in[3];
    const float* W1    = (const float*)d_in[5];
    const float* b1    = (const float*)d_in[6];
    const float* W2    = (const float*)d_in[7];
    const float* b2    = (const float*)d_in[8];
    const float* Ww    = (const float*)d_in[9];
    const float* bw    = (const float*)d_in[10];
    float* out = (float*)d_out;

    cudaFuncSetAttribute(fused_mma_kernel,
                         cudaFuncAttributeMaxDynamicSharedMemorySize, SMEM_TOTAL);

    prep_kernel<<<(HHALF * HID) / 256, 256>>>(W1, out);

    int grid = N_ROWS / MROWS;   // 3125, exact
    fused_mma_kernel<<<grid, NTHREADS, SMEM_TOTAL>>>(h, batch, b1, W2, b2, Ww, bw, out);
}